// round 10
// baseline (speedup 1.0000x reference)
#include <cuda_runtime.h>

#define BSZ 128
#define SEQ 2048
#define NV 64
#define DM 512
#define KC 64
#define NPTS (BSZ*NV)            /* 8192 */
#define PROB_SIZE (NPTS*KC)      /* 524288 */
#define CENT_SIZE (KC*DM)        /* 32768 */
#define XEMB_OFF (PROB_SIZE+CENT_SIZE) /* 557056 */
#define MAX_ITER 10
#define NCHUNK 128               /* one chunk (64 points) per assign block */

#define SMEM_AP (CENT_SIZE*4 + 5248)   /* dynamic smem for fused kernel */

typedef unsigned long long ull;

__device__ __align__(16) float g_cent[CENT_SIZE];
__device__ float g_csq[KC];
__device__ float g_shift[KC];
__device__ int   g_ids[NPTS];
__device__ __align__(16) float g_part[KC*NCHUNK*DM];  /* [k][chunk][d], 16 MB */
__device__ int   g_pcnt[KC*NCHUNK];               /* [k][chunk] */
__device__ int   g_done;

/* ---------- packed fp32x2 helpers (Blackwell) ---------- */
static __device__ __forceinline__ ull pk2(float lo, float hi){
    ull r;
    asm("mov.b64 %0, {%1, %2};" : "=l"(r)
        : "r"(__float_as_uint(lo)), "r"(__float_as_uint(hi)));
    return r;
}
static __device__ __forceinline__ ull fma2(ull a, ull b, ull c){
    ull d;
    asm("fma.rn.f32x2 %0, %1, %2, %3;" : "=l"(d) : "l"(a), "l"(b), "l"(c));
    return d;
}
static __device__ __forceinline__ void upk2(ull v, float &lo, float &hi){
    unsigned int a, b;
    asm("mov.b64 {%0, %1}, %2;" : "=r"(a), "=r"(b) : "l"(v));
    lo = __uint_as_float(a); hi = __uint_as_float(b);
}

/* ---------- prep: copy centroids + csq + reset shift (KC blocks x 512) ---------- */
__global__ void __launch_bounds__(512) prep_kernel(const float* __restrict__ cents){
    __shared__ float red[512];
    const int k = blockIdx.x, t = threadIdx.x;
    float c = cents[k*DM + t];
    g_cent[k*DM + t] = c;
    red[t] = c*c;
    __syncthreads();
    for (int s = 256; s > 0; s >>= 1){ if (t < s) red[t] += red[t+s]; __syncthreads(); }
    if (t == 0){
        g_csq[k] = red[0];
        g_shift[k] = 1.0f;           /* "not converged" sentinel */
        if (k == 0) g_done = 0;
    }
}

/* ---------- main GEMM: x_emb[n,d] = sum_s x[b,s,v]*W[d,s] + b[d] ----------
   128(M) x 128(N) x 16(K) tiles, 256 threads, f32x2 m-pair-packed accumulators,
   double-buffered smem (one sync per k-tile). */
__global__ void __launch_bounds__(256,2) gemm_kernel(const float* __restrict__ x,
                                                     const float* __restrict__ W,
                                                     const float* __restrict__ bias,
                                                     float* __restrict__ xemb){
    __shared__ __align__(16) float As[2][16][128];
    __shared__ __align__(16) float Bs[2][16][128];
    const int tid = threadIdx.x;
    const int d0 = blockIdx.x * 128;
    const int n0 = blockIdx.y * 128;

    int a_m[2], a_c[2], a_base[2];
    int b_d[2], b_s4[2], b_base[2];
#pragma unroll
    for (int j = 0; j < 2; j++){
        int q = j*256 + tid;
        a_m[j] = (q & 31) * 4;
        a_c[j] = q >> 5;
        int gn = n0 + a_m[j];
        a_base[j] = (gn >> 6) * (SEQ*NV) + (gn & 63);
        b_d[j]  = q >> 2;
        b_s4[j] = (q & 3) * 4;
        b_base[j] = (d0 + b_d[j]) * SEQ + b_s4[j];
    }

    ull acc[4][8];
#pragma unroll
    for (int m = 0; m < 4; m++)
#pragma unroll
        for (int j = 0; j < 8; j++) acc[m][j] = 0ull;

    const int tr = tid >> 4, tc = tid & 15;
    const int mb = tr * 8, nb = tc * 8;

    float4 ra[2], rb[2];
#pragma unroll
    for (int j = 0; j < 2; j++){
        ra[j] = *(const float4*)(x + a_base[j] + a_c[j]*NV);
        rb[j] = *(const float4*)(W + b_base[j]);
    }
#pragma unroll
    for (int j = 0; j < 2; j++){
        *(float4*)&As[0][a_c[j]][a_m[j]] = ra[j];
        Bs[0][b_s4[j]+0][b_d[j]] = rb[j].x;
        Bs[0][b_s4[j]+1][b_d[j]] = rb[j].y;
        Bs[0][b_s4[j]+2][b_d[j]] = rb[j].z;
        Bs[0][b_s4[j]+3][b_d[j]] = rb[j].w;
    }
    __syncthreads();

    const int NT = SEQ / 16;
    for (int t = 0; t < NT; t++){
        const int cur = t & 1;
        if (t + 1 < NT){
            int s0 = (t + 1) * 16;
#pragma unroll
            for (int j = 0; j < 2; j++){
                ra[j] = *(const float4*)(x + a_base[j] + (s0 + a_c[j])*NV);
                rb[j] = *(const float4*)(W + b_base[j] + s0);
            }
        }
#pragma unroll
        for (int k = 0; k < 16; k++){
            ulonglong2 A0 = *(const ulonglong2*)&As[cur][k][mb];
            ulonglong2 A1 = *(const ulonglong2*)&As[cur][k][mb+4];
            ull am[4] = {A0.x, A0.y, A1.x, A1.y};
            float4 b0 = *(const float4*)&Bs[cur][k][nb];
            float4 b1 = *(const float4*)&Bs[cur][k][nb+4];
            ull bb[8];
            bb[0] = pk2(b0.x, b0.x); bb[1] = pk2(b0.y, b0.y);
            bb[2] = pk2(b0.z, b0.z); bb[3] = pk2(b0.w, b0.w);
            bb[4] = pk2(b1.x, b1.x); bb[5] = pk2(b1.y, b1.y);
            bb[6] = pk2(b1.z, b1.z); bb[7] = pk2(b1.w, b1.w);
#pragma unroll
            for (int m = 0; m < 4; m++)
#pragma unroll
                for (int j = 0; j < 8; j++)
                    acc[m][j] = fma2(am[m], bb[j], acc[m][j]);
        }
        if (t + 1 < NT){
            const int nxt = cur ^ 1;
#pragma unroll
            for (int j = 0; j < 2; j++){
                *(float4*)&As[nxt][a_c[j]][a_m[j]] = ra[j];
                Bs[nxt][b_s4[j]+0][b_d[j]] = rb[j].x;
                Bs[nxt][b_s4[j]+1][b_d[j]] = rb[j].y;
                Bs[nxt][b_s4[j]+2][b_d[j]] = rb[j].z;
                Bs[nxt][b_s4[j]+3][b_d[j]] = rb[j].w;
            }
        }
        __syncthreads();
    }

    float4 bv0 = *(const float4*)&bias[d0 + nb];
    float4 bv1 = *(const float4*)&bias[d0 + nb + 4];
    float bvals[8] = {bv0.x,bv0.y,bv0.z,bv0.w,bv1.x,bv1.y,bv1.z,bv1.w};
#pragma unroll
    for (int m = 0; m < 4; m++){
        float lo[8], hi[8];
#pragma unroll
        for (int j = 0; j < 8; j++){
            upk2(acc[m][j], lo[j], hi[j]);
            lo[j] += bvals[j]; hi[j] += bvals[j];
        }
        int gn = n0 + mb + 2*m;
        float* r0 = xemb + gn*DM + d0 + nb;
        float* r1 = r0 + DM;
        *(float4*)r0     = make_float4(lo[0],lo[1],lo[2],lo[3]);
        *(float4*)(r0+4) = make_float4(lo[4],lo[5],lo[6],lo[7]);
        *(float4*)r1     = make_float4(hi[0],hi[1],hi[2],hi[3]);
        *(float4*)(r1+4) = make_float4(hi[4],hi[5],hi[6],hi[7]);
    }
}

/* ---------- fused assign + chunk-partial kernel ----------
   128 blocks x 512 threads, block owns 64 points.
   Prologue: done flag from per-k shift (warp 0) + csq gather.
   Phase A: argmin over 64 centroids (8 groups of 8); x_sq in-flight.
   Phase B: deterministic per-chunk segment sums; only rows with count>0
   are written to g_part (combine skips the rest — value-identical). */
__global__ void __launch_bounds__(512,1) assign_partial_kernel(const float* __restrict__ xemb){
    extern __shared__ __align__(16) char sm[];
    float* sums = (float*)sm;                         /* [KC*DM] phase B        */
    float (*xs)[68] = (float(*)[68])sm;               /* phase A overlay        */
    float (*cs)[64] = (float(*)[64])(sm + 64*68*4);
    char* tail = sm + CENT_SIZE*4;
    float* s_xsq    = (float*)tail;                   /* 64 floats              */
    float (*bv)[64] = (float(*)[64])(tail + 256);     /* 8x64 floats            */
    int   (*bi)[64] = (int(*)[64])(tail + 2304);      /* 8x64 ints              */
    int*  sids      = (int*)(tail + 4352);            /* 64 ints                */
    float* s_csq    = (float*)(tail + 4608);          /* 64 floats              */
    int*  s_cnt64   = (int*)(tail + 4864);            /* 64 ints                */
    int*  s_done    = (int*)(tail + 5120);

    const int tid = threadIdx.x;
    const int blk = blockIdx.x;
    const int base_p = blk * 64;
    const int pl = tid & 63;
    const int g  = tid >> 6;                          /* 0..7 */

    /* ---- prologue: done flag (deterministic) + csq gather ---- */
    if (tid < 32){
        float s = g_shift[tid] + g_shift[tid + 32];
#pragma unroll
        for (int off = 16; off > 0; off >>= 1) s += __shfl_down_sync(0xffffffffu, s, off);
        if (tid == 0){
            int dn = (s < 1e-8f) ? 1 : 0;   /* ||shift|| < 1e-4 <=> sumsq < 1e-8 */
            *s_done = dn;
            g_done = dn;
        }
    } else if (tid >= 64 && tid < 128){
        s_csq[tid - 64] = g_csq[tid - 64];
    }
    __syncthreads();
    if (*s_done) return;

    /* ---- phase A ---- */
    ull acc2[8];
#pragma unroll
    for (int i = 0; i < 8; i++) acc2[i] = 0ull;
    ull xacc = 0ull;

    for (int d0 = 0; d0 < DM; d0 += 64){
#pragma unroll
        for (int j = 0; j < 2; j++){
            int q = j*512 + tid;          /* 0..1023 */
            int r = q >> 4;               /* 0..63   */
            int c4 = (q & 15) * 4;
            float4 v = *(const float4*)(xemb + (base_p + r)*DM + d0 + c4);
            *(float4*)&xs[r][c4] = v;
            float4 w = *(const float4*)(&g_cent[r*DM + d0 + c4]);
            *(float4*)&cs[r][c4] = w;
        }
        __syncthreads();
#pragma unroll
        for (int dd = 0; dd < 64; dd += 8){
            ulonglong2 X0 = *(const ulonglong2*)&xs[pl][dd];
            ulonglong2 X1 = *(const ulonglong2*)&xs[pl][dd+4];
#pragma unroll
            for (int kk = 0; kk < 8; kk++){
                const float* cp = &cs[g*8 + kk][dd];
                ulonglong2 C0 = *(const ulonglong2*)cp;
                ulonglong2 C1 = *(const ulonglong2*)(cp + 4);
                ull a = acc2[kk];
                a = fma2(X0.x, C0.x, a);
                a = fma2(X0.y, C0.y, a);
                a = fma2(X1.x, C1.x, a);
                a = fma2(X1.y, C1.y, a);
                acc2[kk] = a;
            }
            if (g == 0){                  /* warps 0-1: x_sq in-flight */
                xacc = fma2(X0.x, X0.x, xacc);
                xacc = fma2(X0.y, X0.y, xacc);
                xacc = fma2(X1.x, X1.x, xacc);
                xacc = fma2(X1.y, X1.y, xacc);
            }
        }
        __syncthreads();
    }
    if (g == 0){
        float lo, hi; upk2(xacc, lo, hi);
        s_xsq[pl] = lo + hi;
    }
    __syncthreads();

    float xq = s_xsq[pl];
    float best = 3.4e38f;
    int bk = 0;
#pragma unroll
    for (int kk = 0; kk < 8; kk++){
        int k = g*8 + kk;
        float lo, hi; upk2(acc2[kk], lo, hi);
        float d2v = (xq - 2.0f*(lo + hi)) + s_csq[k];
        if (d2v < best){ best = d2v; bk = k; }
    }
    bv[g][pl] = best; bi[g][pl] = bk;
    __syncthreads();
    if (g == 0){
#pragma unroll
        for (int gg = 1; gg < 8; gg++){
            float v = bv[gg][pl];
            if (v < best){ best = v; bk = bi[gg][pl]; }
        }
        sids[pl] = bk;
        g_ids[base_p + pl] = bk;
    }
    __syncthreads();

    /* counts first (needed to guard the partial writes) */
    if (tid < KC){
        int c = 0;
#pragma unroll
        for (int p = 0; p < 64; p++) c += (sids[p] == tid);
        s_cnt64[tid] = c;
        g_pcnt[tid*NCHUNK + blk] = c;
    }

    /* ---- phase B: chunk partial sums (deterministic ascending p) ---- */
#pragma unroll
    for (int i = 0; i < 16; i++)
        *(float4*)&sums[(i*512 + tid)*4] = make_float4(0.f,0.f,0.f,0.f);
    __syncthreads();

    const int d = tid;                    /* 0..511: one dim per thread */
#pragma unroll 4
    for (int p = 0; p < 64; p++){
        int id = sids[p];
        sums[id*DM + d] += xemb[(base_p + p)*DM + d];
    }
    __syncthreads();
    /* write only non-empty cluster rows to g_part[k][blk][d] */
#pragma unroll
    for (int i = 0; i < 16; i++){
        int f4 = i*512 + tid;             /* 0..8191 */
        int k  = f4 >> 7;                 /* 0..63   */
        int d4 = f4 & 127;                /* 0..127  */
        if (s_cnt64[k])
            *(float4*)&g_part[(k*NCHUNK + blk)*DM + d4*4] = *(const float4*)&sums[f4*4];
    }
}

/* ---------- combine: KC blocks x 512 threads, one dim per thread ----------
   Compacted nonzero-chunk list; 8-deep load batches; accumulation order is
   strictly ascending chunk index (value-identical to the dense version). */
__global__ void __launch_bounds__(512) combine_kernel(){
    if (g_done) return;
    __shared__ int   scnt[NCHUNK];
    __shared__ short slist[NCHUNK];
    __shared__ int   s_nnz, s_cnt;
    __shared__ float reds[512];
    __shared__ float redc[512];
    const int k = blockIdx.x, t = threadIdx.x;
    if (t < NCHUNK) scnt[t] = g_pcnt[k*NCHUNK + t];
    __syncthreads();
    if (t == 0){
        int nn = 0, c = 0;
        for (int b = 0; b < NCHUNK; b++){
            int v = scnt[b];
            if (v){ slist[nn++] = (short)b; c += v; }
        }
        s_nnz = nn; s_cnt = c;
    }
    __syncthreads();
    const int nnz = s_nnz, cnt = s_cnt;
    const float* base = &g_part[(size_t)k*NCHUNK*DM + t];

    float s = 0.f;
    int j = 0;
    for (; j + 8 <= nnz; j += 8){
        float r[8];
#pragma unroll
        for (int u = 0; u < 8; u++) r[u] = __ldcg(base + (int)slist[j+u]*DM);
#pragma unroll
        for (int u = 0; u < 8; u++) s += r[u];
    }
    for (; j < nnz; j++) s += __ldcg(base + (int)slist[j]*DM);

    float old = g_cent[k*DM + t];
    float nc = (cnt > 0) ? s / (float)cnt : old;
    g_cent[k*DM + t] = nc;
    float df = nc - old;
    reds[t] = df*df;
    redc[t] = nc*nc;
    __syncthreads();
    for (int r = 256; r > 0; r >>= 1){
        if (t < r){ reds[t] += reds[t+r]; redc[t] += redc[t+r]; }
        __syncthreads();
    }
    if (t == 0){
        g_shift[k] = reds[0];
        g_csq[k]   = redc[0];
    }
}

/* ---------- outputs: one-hot prob + centroid copy (128 blocks x 256) ---------- */
__global__ void output_kernel(float* __restrict__ out){
    const int gt = blockIdx.x*256 + threadIdx.x;    /* 0..32767 */
    if (gt < NPTS){
        int id = g_ids[gt];
        float4* o = (float4*)(out + (size_t)gt*KC);
        int jv = id >> 2, comp = id & 3;
#pragma unroll
        for (int j = 0; j < 16; j++){
            float4 z = make_float4(0.f,0.f,0.f,0.f);
            if (j == jv) (&z.x)[comp] = 1.0f;
            o[j] = z;
        }
    }
    out[PROB_SIZE + gt] = g_cent[gt];
}

extern "C" void kernel_launch(void* const* d_in, const int* in_sizes, int n_in,
                              void* d_out, int out_size){
    const float* x     = (const float*)d_in[0];   /* [128,2048,64] */
    const float* W     = (const float*)d_in[1];   /* [512,2048]    */
    const float* bias  = (const float*)d_in[2];   /* [512]         */
    const float* cents = (const float*)d_in[3];   /* [64,512]      */
    float* out  = (float*)d_out;
    float* xemb = out + XEMB_OFF;

    cudaFuncSetAttribute((const void*)assign_partial_kernel,
                         cudaFuncAttributeMaxDynamicSharedMemorySize, SMEM_AP);

    prep_kernel<<<KC, 512>>>(cents);
    gemm_kernel<<<dim3(DM/128, NPTS/128), 256>>>(x, W, bias, xemb);

    for (int it = 0; it < MAX_ITER; it++){
        assign_partial_kernel<<<NCHUNK, 512, SMEM_AP>>>(xemb);
        combine_kernel<<<KC, 512>>>();
    }
    output_kernel<<<NPTS/64, 256>>>(out);
}

// round 15
// speedup vs baseline: 1.0884x; 1.0884x over previous
#include <cuda_runtime.h>

#define BSZ 128
#define SEQ 2048
#define NV 64
#define DM 512
#define KC 64
#define NPTS (BSZ*NV)            /* 8192 */
#define PROB_SIZE (NPTS*KC)      /* 524288 */
#define CENT_SIZE (KC*DM)        /* 32768 */
#define XEMB_OFF (PROB_SIZE+CENT_SIZE) /* 557056 */
#define MAX_ITER 10
#define NCHUNK 128               /* one chunk (64 points) per assign block */

#define SMEM_AP (CENT_SIZE*4 + 4880)   /* 135952 B dynamic smem for fused kernel */

typedef unsigned long long ull;

__device__ __align__(16) float g_cent[CENT_SIZE];
__device__ float g_csqp[KC*4];                    /* per-(k,dg) csq partials   */
__device__ float g_shiftp[KC*4];                  /* per-(k,dg) shift partials */
__device__ int   g_ids[NPTS];
__device__ __align__(16) float g_part[KC*NCHUNK*DM];  /* [k][chunk][d], 16 MB */
__device__ int   g_pcnt[KC*NCHUNK];               /* [k][chunk] */
__device__ int   g_done;

/* ---------- packed fp32x2 helpers (Blackwell) ---------- */
static __device__ __forceinline__ ull pk2(float lo, float hi){
    ull r;
    asm("mov.b64 %0, {%1, %2};" : "=l"(r)
        : "r"(__float_as_uint(lo)), "r"(__float_as_uint(hi)));
    return r;
}
static __device__ __forceinline__ ull fma2(ull a, ull b, ull c){
    ull d;
    asm("fma.rn.f32x2 %0, %1, %2, %3;" : "=l"(d) : "l"(a), "l"(b), "l"(c));
    return d;
}
static __device__ __forceinline__ void upk2(ull v, float &lo, float &hi){
    unsigned int a, b;
    asm("mov.b64 {%0, %1}, %2;" : "=r"(a), "=r"(b) : "l"(v));
    lo = __uint_as_float(a); hi = __uint_as_float(b);
}

/* ---------- prep: copy centroids, per-(k,dg) csq partials, reset shift ----
   grid (KC,4) x 128 threads, mirroring combine's reduction layout. */
__global__ void prep_kernel(const float* __restrict__ cents){
    __shared__ float red[128];
    const int k = blockIdx.x, dg = blockIdx.y, t = threadIdx.x;
    const int dim = dg*128 + t;
    float c = cents[k*DM + dim];
    g_cent[k*DM + dim] = c;
    red[t] = c*c;
    __syncthreads();
    for (int s = 64; s > 0; s >>= 1){ if (t < s) red[t] += red[t+s]; __syncthreads(); }
    if (t == 0){
        g_csqp[k*4 + dg] = red[0];
        g_shiftp[k*4 + dg] = 1.0f;     /* "not converged" sentinel */
        if (k == 0 && dg == 0) g_done = 0;
    }
}

/* ---------- main GEMM: x_emb[n,d] = sum_s x[b,s,v]*W[d,s] + b[d] ----------
   128(M) x 128(N) x 16(K) tiles, 256 threads, f32x2 m-pair-packed accumulators,
   double-buffered smem (one sync per k-tile). */
__global__ void __launch_bounds__(256,2) gemm_kernel(const float* __restrict__ x,
                                                     const float* __restrict__ W,
                                                     const float* __restrict__ bias,
                                                     float* __restrict__ xemb){
    __shared__ __align__(16) float As[2][16][128];
    __shared__ __align__(16) float Bs[2][16][128];
    const int tid = threadIdx.x;
    const int d0 = blockIdx.x * 128;
    const int n0 = blockIdx.y * 128;

    int a_m[2], a_c[2], a_base[2];
    int b_d[2], b_s4[2], b_base[2];
#pragma unroll
    for (int j = 0; j < 2; j++){
        int q = j*256 + tid;
        a_m[j] = (q & 31) * 4;
        a_c[j] = q >> 5;
        int gn = n0 + a_m[j];
        a_base[j] = (gn >> 6) * (SEQ*NV) + (gn & 63);
        b_d[j]  = q >> 2;
        b_s4[j] = (q & 3) * 4;
        b_base[j] = (d0 + b_d[j]) * SEQ + b_s4[j];
    }

    ull acc[4][8];
#pragma unroll
    for (int m = 0; m < 4; m++)
#pragma unroll
        for (int j = 0; j < 8; j++) acc[m][j] = 0ull;

    const int tr = tid >> 4, tc = tid & 15;
    const int mb = tr * 8, nb = tc * 8;

    float4 ra[2], rb[2];
#pragma unroll
    for (int j = 0; j < 2; j++){
        ra[j] = *(const float4*)(x + a_base[j] + a_c[j]*NV);
        rb[j] = *(const float4*)(W + b_base[j]);
    }
#pragma unroll
    for (int j = 0; j < 2; j++){
        *(float4*)&As[0][a_c[j]][a_m[j]] = ra[j];
        Bs[0][b_s4[j]+0][b_d[j]] = rb[j].x;
        Bs[0][b_s4[j]+1][b_d[j]] = rb[j].y;
        Bs[0][b_s4[j]+2][b_d[j]] = rb[j].z;
        Bs[0][b_s4[j]+3][b_d[j]] = rb[j].w;
    }
    __syncthreads();

    const int NT = SEQ / 16;
    for (int t = 0; t < NT; t++){
        const int cur = t & 1;
        if (t + 1 < NT){
            int s0 = (t + 1) * 16;
#pragma unroll
            for (int j = 0; j < 2; j++){
                ra[j] = *(const float4*)(x + a_base[j] + (s0 + a_c[j])*NV);
                rb[j] = *(const float4*)(W + b_base[j] + s0);
            }
        }
#pragma unroll
        for (int k = 0; k < 16; k++){
            ulonglong2 A0 = *(const ulonglong2*)&As[cur][k][mb];
            ulonglong2 A1 = *(const ulonglong2*)&As[cur][k][mb+4];
            ull am[4] = {A0.x, A0.y, A1.x, A1.y};
            float4 b0 = *(const float4*)&Bs[cur][k][nb];
            float4 b1 = *(const float4*)&Bs[cur][k][nb+4];
            ull bb[8];
            bb[0] = pk2(b0.x, b0.x); bb[1] = pk2(b0.y, b0.y);
            bb[2] = pk2(b0.z, b0.z); bb[3] = pk2(b0.w, b0.w);
            bb[4] = pk2(b1.x, b1.x); bb[5] = pk2(b1.y, b1.y);
            bb[6] = pk2(b1.z, b1.z); bb[7] = pk2(b1.w, b1.w);
#pragma unroll
            for (int m = 0; m < 4; m++)
#pragma unroll
                for (int j = 0; j < 8; j++)
                    acc[m][j] = fma2(am[m], bb[j], acc[m][j]);
        }
        if (t + 1 < NT){
            const int nxt = cur ^ 1;
#pragma unroll
            for (int j = 0; j < 2; j++){
                *(float4*)&As[nxt][a_c[j]][a_m[j]] = ra[j];
                Bs[nxt][b_s4[j]+0][b_d[j]] = rb[j].x;
                Bs[nxt][b_s4[j]+1][b_d[j]] = rb[j].y;
                Bs[nxt][b_s4[j]+2][b_d[j]] = rb[j].z;
                Bs[nxt][b_s4[j]+3][b_d[j]] = rb[j].w;
            }
        }
        __syncthreads();
    }

    float4 bv0 = *(const float4*)&bias[d0 + nb];
    float4 bv1 = *(const float4*)&bias[d0 + nb + 4];
    float bvals[8] = {bv0.x,bv0.y,bv0.z,bv0.w,bv1.x,bv1.y,bv1.z,bv1.w};
#pragma unroll
    for (int m = 0; m < 4; m++){
        float lo[8], hi[8];
#pragma unroll
        for (int j = 0; j < 8; j++){
            upk2(acc[m][j], lo[j], hi[j]);
            lo[j] += bvals[j]; hi[j] += bvals[j];
        }
        int gn = n0 + mb + 2*m;
        float* r0 = xemb + gn*DM + d0 + nb;
        float* r1 = r0 + DM;
        *(float4*)r0     = make_float4(lo[0],lo[1],lo[2],lo[3]);
        *(float4*)(r0+4) = make_float4(lo[4],lo[5],lo[6],lo[7]);
        *(float4*)r1     = make_float4(hi[0],hi[1],hi[2],hi[3]);
        *(float4*)(r1+4) = make_float4(hi[4],hi[5],hi[6],hi[7]);
    }
}

/* ---------- fused assign + chunk-partial kernel ----------
   128 blocks x 512 threads, block owns 64 points.
   Prologue: done flag from shift partials (warp 0) + csq from partials.
   Phase A: argmin over 64 centroids (8 groups of 8); x_sq in-flight.
   Phase B: deterministic per-chunk segment sums in smem -> g_part. */
__global__ void __launch_bounds__(512,1) assign_partial_kernel(const float* __restrict__ xemb){
    extern __shared__ __align__(16) char sm[];
    float* sums = (float*)sm;                         /* [KC*DM] phase B        */
    float (*xs)[68] = (float(*)[68])sm;               /* phase A overlay        */
    float (*cs)[64] = (float(*)[64])(sm + 64*68*4);
    char* tail = sm + CENT_SIZE*4;
    float* s_xsq    = (float*)tail;                   /* 64 floats              */
    float (*bv)[64] = (float(*)[64])(tail + 256);     /* 8x64 floats            */
    int   (*bi)[64] = (int(*)[64])(tail + 2304);      /* 8x64 ints              */
    int*  sids      = (int*)(tail + 4352);            /* 64 ints                */
    float* s_csq    = (float*)(tail + 4608);          /* 64 floats              */
    int*  s_done    = (int*)(tail + 4864);

    const int tid = threadIdx.x;
    const int blk = blockIdx.x;
    const int base_p = blk * 64;
    const int pl = tid & 63;
    const int g  = tid >> 6;                          /* 0..7 */

    /* ---- prologue: done flag (deterministic) + csq gather ---- */
    if (tid < 32){
        float s = 0.f;
#pragma unroll
        for (int j = 0; j < 8; j++) s += g_shiftp[tid + j*32];
#pragma unroll
        for (int off = 16; off > 0; off >>= 1) s += __shfl_down_sync(0xffffffffu, s, off);
        if (tid == 0){
            int dn = (s < 1e-8f) ? 1 : 0;   /* ||shift|| < 1e-4 <=> sumsq < 1e-8 */
            *s_done = dn;
            g_done = dn;
        }
    } else if (tid >= 64 && tid < 128){
        int k = tid - 64;
        const float* cp = &g_csqp[k*4];
        s_csq[k] = ((cp[0] + cp[1]) + cp[2]) + cp[3];
    }
    __syncthreads();
    if (*s_done) return;

    /* ---- phase A ---- */
    ull acc2[8];
#pragma unroll
    for (int i = 0; i < 8; i++) acc2[i] = 0ull;
    ull xacc = 0ull;

    for (int d0 = 0; d0 < DM; d0 += 64){
#pragma unroll
        for (int j = 0; j < 2; j++){
            int q = j*512 + tid;          /* 0..1023 */
            int r = q >> 4;               /* 0..63   */
            int c4 = (q & 15) * 4;
            float4 v = *(const float4*)(xemb + (base_p + r)*DM + d0 + c4);
            *(float4*)&xs[r][c4] = v;
            float4 w = *(const float4*)(&g_cent[r*DM + d0 + c4]);
            *(float4*)&cs[r][c4] = w;
        }
        __syncthreads();
#pragma unroll
        for (int dd = 0; dd < 64; dd += 8){
            ulonglong2 X0 = *(const ulonglong2*)&xs[pl][dd];
            ulonglong2 X1 = *(const ulonglong2*)&xs[pl][dd+4];
#pragma unroll
            for (int kk = 0; kk < 8; kk++){
                const float* cp = &cs[g*8 + kk][dd];
                ulonglong2 C0 = *(const ulonglong2*)cp;
                ulonglong2 C1 = *(const ulonglong2*)(cp + 4);
                ull a = acc2[kk];
                a = fma2(X0.x, C0.x, a);
                a = fma2(X0.y, C0.y, a);
                a = fma2(X1.x, C1.x, a);
                a = fma2(X1.y, C1.y, a);
                acc2[kk] = a;
            }
            if (g == 0){                  /* warps 0-1: x_sq in-flight */
                xacc = fma2(X0.x, X0.x, xacc);
                xacc = fma2(X0.y, X0.y, xacc);
                xacc = fma2(X1.x, X1.x, xacc);
                xacc = fma2(X1.y, X1.y, xacc);
            }
        }
        __syncthreads();
    }
    if (g == 0){
        float lo, hi; upk2(xacc, lo, hi);
        s_xsq[pl] = lo + hi;
    }
    __syncthreads();

    float xq = s_xsq[pl];
    float best = 3.4e38f;
    int bk = 0;
#pragma unroll
    for (int kk = 0; kk < 8; kk++){
        int k = g*8 + kk;
        float lo, hi; upk2(acc2[kk], lo, hi);
        float d2v = (xq - 2.0f*(lo + hi)) + s_csq[k];
        if (d2v < best){ best = d2v; bk = k; }
    }
    bv[g][pl] = best; bi[g][pl] = bk;
    __syncthreads();
    if (g == 0){
#pragma unroll
        for (int gg = 1; gg < 8; gg++){
            float v = bv[gg][pl];
            if (v < best){ best = v; bk = bi[gg][pl]; }
        }
        sids[pl] = bk;
        g_ids[base_p + pl] = bk;
    }
    __syncthreads();

    /* ---- phase B: chunk partial sums (deterministic ascending p) ---- */
#pragma unroll
    for (int i = 0; i < 16; i++)
        *(float4*)&sums[(i*512 + tid)*4] = make_float4(0.f,0.f,0.f,0.f);
    __syncthreads();

    const int d = tid;                    /* 0..511: one dim per thread */
#pragma unroll 4
    for (int p = 0; p < 64; p++){
        int id = sids[p];
        sums[id*DM + d] += xemb[(base_p + p)*DM + d];
    }
    __syncthreads();
    /* write to transposed layout g_part[k][blk][d] */
#pragma unroll
    for (int i = 0; i < 16; i++){
        int f4 = i*512 + tid;             /* 0..8191 */
        int k  = f4 >> 7;                 /* 0..63   */
        int d4 = f4 & 127;                /* 0..127  */
        *(float4*)&g_part[(k*NCHUNK + blk)*DM + d4*4] = *(const float4*)&sums[f4*4];
    }
    if (tid < KC){
        int c = 0;
#pragma unroll
        for (int p = 0; p < 64; p++) c += (sids[p] == tid);
        g_pcnt[tid*NCHUNK + blk] = c;
    }
}

/* ---------- combine: grid (KC,4) x 512 threads ----------
   4 warp-groups x 128 dims; each warp-group sums 32 chunks (ascending, 8-deep
   load batches), then fixed-order join ((wg0+wg1)+wg2)+wg3. */
__global__ void __launch_bounds__(512) combine_kernel(){
    if (g_done) return;
    __shared__ float s_part[4][128];
    __shared__ int   scnt[128];
    __shared__ float reds[128];
    __shared__ float redc[128];
    const int k = blockIdx.x, dg = blockIdx.y, t = threadIdx.x;
    const int wg = t >> 7, ln = t & 127;
    const int dim = dg*128 + ln;
    const float* base = &g_part[(size_t)k*NCHUNK*DM + dim];

    float s = 0.f;
    const int b0 = wg*32;
#pragma unroll
    for (int j = 0; j < 32; j += 8){
        float r[8];
#pragma unroll
        for (int u = 0; u < 8; u++) r[u] = __ldcg(base + (b0 + j + u)*DM);
#pragma unroll
        for (int u = 0; u < 8; u++) s += r[u];
    }
    s_part[wg][ln] = s;
    if (t < 128) scnt[t] = g_pcnt[k*NCHUNK + t];
    __syncthreads();
    for (int r2 = 64; r2 > 0; r2 >>= 1){
        if (t < r2) scnt[t] += scnt[t + r2];
        __syncthreads();
    }
    const int cnt = scnt[0];

    if (t < 128){
        float sum = ((s_part[0][t] + s_part[1][t]) + s_part[2][t]) + s_part[3][t];
        float old = g_cent[k*DM + dg*128 + t];
        float nc = (cnt > 0) ? sum / (float)cnt : old;
        g_cent[k*DM + dg*128 + t] = nc;
        float df = nc - old;
        reds[t] = df*df;
        redc[t] = nc*nc;
    }
    __syncthreads();
    for (int r2 = 64; r2 > 0; r2 >>= 1){
        if (t < r2){ reds[t] += reds[t+r2]; redc[t] += redc[t+r2]; }
        __syncthreads();
    }
    if (t == 0){
        g_shiftp[k*4 + dg] = reds[0];
        g_csqp[k*4 + dg]  = redc[0];
    }
}

/* ---------- outputs: one-hot prob + centroid copy (128 blocks x 256) ---------- */
__global__ void output_kernel(float* __restrict__ out){
    const int gt = blockIdx.x*256 + threadIdx.x;    /* 0..32767 */
    if (gt < NPTS){
        int id = g_ids[gt];
        float4* o = (float4*)(out + (size_t)gt*KC);
        int jv = id >> 2, comp = id & 3;
#pragma unroll
        for (int j = 0; j < 16; j++){
            float4 z = make_float4(0.f,0.f,0.f,0.f);
            if (j == jv) (&z.x)[comp] = 1.0f;
            o[j] = z;
        }
    }
    out[PROB_SIZE + gt] = g_cent[gt];
}

extern "C" void kernel_launch(void* const* d_in, const int* in_sizes, int n_in,
                              void* d_out, int out_size){
    const float* x     = (const float*)d_in[0];   /* [128,2048,64] */
    const float* W     = (const float*)d_in[1];   /* [512,2048]    */
    const float* bias  = (const float*)d_in[2];   /* [512]         */
    const float* cents = (const float*)d_in[3];   /* [64,512]      */
    float* out  = (float*)d_out;
    float* xemb = out + XEMB_OFF;

    cudaFuncSetAttribute((const void*)assign_partial_kernel,
                         cudaFuncAttributeMaxDynamicSharedMemorySize, SMEM_AP);

    prep_kernel<<<dim3(KC,4), 128>>>(cents);
    gemm_kernel<<<dim3(DM/128, NPTS/128), 256>>>(x, W, bias, xemb);

    for (int it = 0; it < MAX_ITER; it++){
        assign_partial_kernel<<<NCHUNK, 512, SMEM_AP>>>(xemb);
        combine_kernel<<<dim3(KC,4), 512>>>();
    }
    output_kernel<<<NPTS/64, 256>>>(out);
}